// round 5
// baseline (speedup 1.0000x reference)
#include <cuda_runtime.h>

#define B 64
#define CIN 512
#define HIDE 128
#define OP 512
#define HW 4096   // 64*64

// scratch for pooled y [B, CIN]
__device__ float g_y[B * CIN];

__device__ __forceinline__ void prefetch_l2(const void* p) {
    asm volatile("prefetch.global.L2 [%0];" :: "l"(p));
}

// ---------------------------------------------------------------------------
// Kernel 1: global average pool. One WARP per (b,c) row of 4096 floats:
// 32 float4 loads per lane (streaming), shuffle reduce, no smem, no barriers.
// 4096 blocks x 8 warps = 32768 rows.
// ---------------------------------------------------------------------------
__global__ __launch_bounds__(256) void pool_kernel(const float* __restrict__ x,
                                                   float* __restrict__ y) {
    cudaTriggerProgrammaticLaunchCompletion();

    const int lane = threadIdx.x & 31;
    const int row  = (blockIdx.x << 3) + (threadIdx.x >> 5);

    const float4* p = reinterpret_cast<const float4*>(x + (size_t)row * HW);

    float s = 0.0f;
#pragma unroll 8
    for (int i = 0; i < 32; i++) {
        float4 v = __ldcs(&p[lane + (i << 5)]);
        s += (v.x + v.y) + (v.z + v.w);
    }

#pragma unroll
    for (int o = 16; o > 0; o >>= 1) s += __shfl_xor_sync(0xFFFFFFFFu, s, o);

    if (lane == 0) y[row] = s * (1.0f / (float)HW);
}

// ---------------------------------------------------------------------------
// Kernel 2: fully fused AGCA head. One block per batch, 1024 threads.
// Launched with PDL: prefetches its weight slice into L2 BEFORE the grid
// dependency resolves, then syncs and computes.
// ---------------------------------------------------------------------------
__global__ __launch_bounds__(1024) void head_kernel(const float* __restrict__ y,
                                                    const float* __restrict__ W1,
                                                    const float* __restrict__ A2,
                                                    const float* __restrict__ w2p,
                                                    const float* __restrict__ w3p,
                                                    const float* __restrict__ W4,
                                                    float* __restrict__ out) {
    const int b    = blockIdx.x;
    const int tid  = threadIdx.x;
    const int wid  = tid >> 5;
    const int lane = tid & 31;

    // ---- L2 prefetch of this block's 1/64 slice of the weights ----
    {
        const char* w1c = (const char*)W1;
        const char* w4c = (const char*)W4;
        const char* a2c = (const char*)A2;
        if (tid < 32) {
            prefetch_l2(w1c + ((size_t)b * 32 + tid) * 128);
        } else if (tid < 64) {
            prefetch_l2(w4c + ((size_t)b * 32 + (tid - 32)) * 128);
        } else if (tid < 72) {
            prefetch_l2(a2c + ((size_t)b * 8 + (tid - 64)) * 128);
        }
    }

    cudaGridDependencySynchronize();

    __shared__ float ys[CIN];
    __shared__ float y1s[HIDE];
    __shared__ float a1s[HIDE];
    __shared__ float y3s[HIDE];
    __shared__ float red[8];

    if (tid < CIN) ys[tid] = y[b * CIN + tid];
    __syncthreads();

    // ---- GEMV1: warp wid -> h = wid*4 + {0..3}; batched loads ----
    {
        const int h0 = wid << 2;
        const float* r0 = W1 + (size_t)(h0 + 0) * CIN;
        const float* r1 = W1 + (size_t)(h0 + 1) * CIN;
        const float* r2 = W1 + (size_t)(h0 + 2) * CIN;
        const float* r3 = W1 + (size_t)(h0 + 3) * CIN;
        float a0 = 0.f, a1 = 0.f, a2 = 0.f, a3 = 0.f;
#pragma unroll
        for (int k = 0; k < CIN / 32; k++) {
            const int c = lane + (k << 5);
            const float yv = ys[c];
            a0 += yv * __ldg(r0 + c);
            a1 += yv * __ldg(r1 + c);
            a2 += yv * __ldg(r2 + c);
            a3 += yv * __ldg(r3 + c);
        }
#pragma unroll
        for (int o = 16; o > 0; o >>= 1) {
            a0 += __shfl_xor_sync(0xFFFFFFFFu, a0, o);
            a1 += __shfl_xor_sync(0xFFFFFFFFu, a1, o);
            a2 += __shfl_xor_sync(0xFFFFFFFFu, a2, o);
            a3 += __shfl_xor_sync(0xFFFFFFFFu, a3, o);
        }
        if (lane == 0) {
            y1s[h0 + 0] = a0; y1s[h0 + 1] = a1;
            y1s[h0 + 2] = a2; y1s[h0 + 3] = a3;
        }
    }
    __syncthreads();

    // ---- softmax(w2 * y1) over 128 channels (first 4 warps) ----
    const float w2 = __ldg(w2p);
    if (tid < HIDE) {
        const float z = w2 * y1s[tid];
        float m = z;
#pragma unroll
        for (int o = 16; o > 0; o >>= 1) m = fmaxf(m, __shfl_xor_sync(0xFFFFFFFFu, m, o));
        if (lane == 0) red[wid] = m;
    }
    __syncthreads();
    if (tid < HIDE) {
        const float m = fmaxf(fmaxf(red[0], red[1]), fmaxf(red[2], red[3]));
        const float e = expf(w2 * y1s[tid] - m);
        a1s[tid] = e;
        float ssum = e;
#pragma unroll
        for (int o = 16; o > 0; o >>= 1) ssum += __shfl_xor_sync(0xFFFFFFFFu, ssum, o);
        if (lane == 0) red[4 + wid] = ssum;
    }
    __syncthreads();

    // ---- y2/y3: h = tid (<128); A2 coalesced over h ----
    if (tid < HIDE) {
        const float ssum = (red[4] + red[5]) + (red[6] + red[7]);
        const float a1n = a1s[tid] / ssum;
        float t = y1s[tid] * a1n;
#pragma unroll 16
        for (int j = 0; j < HIDE; j++) t += y1s[j] * __ldg(&A2[j * HIDE + tid]);
        const float w3 = __ldg(w3p);
        y3s[tid] = fmaxf(w3 * t, 0.0f);
    }
    __syncthreads();

    // ---- GEMV4: warp wid owns outputs wid*16..wid*16+15 (2 passes of 8) ----
#pragma unroll
    for (int pass = 0; pass < 2; pass++) {
        const int o_base = (wid << 4) + (pass << 3);
        float acc[8];
#pragma unroll
        for (int i = 0; i < 8; i++) acc[i] = 0.0f;
#pragma unroll
        for (int k = 0; k < HIDE / 32; k++) {
            const int j = lane + (k << 5);
            const float yv = y3s[j];
#pragma unroll
            for (int i = 0; i < 8; i++)
                acc[i] += yv * __ldg(&W4[(size_t)(o_base + i) * HIDE + j]);
        }
#pragma unroll
        for (int off = 16; off > 0; off >>= 1) {
#pragma unroll
            for (int i = 0; i < 8; i++)
                acc[i] += __shfl_xor_sync(0xFFFFFFFFu, acc[i], off);
        }
        if (lane == 0) {
#pragma unroll
            for (int i = 0; i < 8; i++)
                out[b * OP + o_base + i] = 1.0f / (1.0f + expf(-acc[i]));
        }
    }
}

extern "C" void kernel_launch(void* const* d_in, const int* in_sizes, int n_in,
                              void* d_out, int out_size) {
    const float* x  = (const float*)d_in[0];
    const float* W1 = (const float*)d_in[1];
    const float* A2 = (const float*)d_in[2];
    const float* w2 = (const float*)d_in[3];
    const float* w3 = (const float*)d_in[4];
    const float* W4 = (const float*)d_in[5];
    float* out = (float*)d_out;

    float* yscratch;
    cudaGetSymbolAddress((void**)&yscratch, g_y);

    pool_kernel<<<(B * CIN) / 8, 256>>>(x, yscratch);

    cudaLaunchConfig_t cfg = {};
    cfg.gridDim = dim3(B);
    cfg.blockDim = dim3(1024);
    cfg.dynamicSmemBytes = 0;
    cfg.stream = 0;
    cudaLaunchAttribute attr[1];
    attr[0].id = cudaLaunchAttributeProgrammaticStreamSerialization;
    attr[0].val.programmaticStreamSerializationAllowed = 1;
    cfg.attrs = attr;
    cfg.numAttrs = 1;
    cudaLaunchKernelEx(&cfg, head_kernel, (const float*)yscratch, W1, A2, w2, w3, W4, out);
}